// round 13
// baseline (speedup 1.0000x reference)
#include <cuda_runtime.h>
#include <cuda_bf16.h>
#include <cstdint>

// ---------------------------------------------------------------------------
// StackRNN v13 = v12 topology (best: 740us) with smem-crossbar pressure cut:
//  (1) soft stack lives in the update warps' REGISTERS (8 float4/lane);
//      per step: 8 SHFL boundary exchange + publish rows 1-3 (48B) only.
//      Full stack never transits smem; final stack STG'd from registers.
//  (2) sZs deleted: state-softmax Z folded into consumers' dot loads
//      (16 fadd2); state warps' producer tail is a single STS.
//
// Group A (warps 0-7, 256 thr): 4 state + 2 mem + 2 update. bar.sync(1,256)
//   per step. DEPTH-4 slot ring feeding Group B.
// Group B (warps 8-15, 256 thr): buffer-logit warps, lag <=3 steps.
//   Per slot s: ready barrier 2+s (A arrives, B syncs), free 6+s.
// ---------------------------------------------------------------------------

#define NOUT 210
#define B_TOT 256
#define SEQ 1024
#define NTHREADS 512

#define BAR_SYNC(id, cnt)   asm volatile("bar.sync %0, %1;"   :: "r"(id), "r"(cnt) : "memory")
#define BAR_ARRIVE(id, cnt) asm volatile("bar.arrive %0, %1;" :: "r"(id), "r"(cnt) : "memory")

typedef unsigned long long ull;

__device__ __forceinline__ ull ffma2(ull a, ull b, ull c) {
    ull d; asm("fma.rn.f32x2 %0,%1,%2,%3;" : "=l"(d) : "l"(a), "l"(b), "l"(c)); return d;
}
__device__ __forceinline__ ull fadd2(ull a, ull b) {
    ull d; asm("add.rn.f32x2 %0,%1,%2;" : "=l"(d) : "l"(a), "l"(b)); return d;
}
__device__ __forceinline__ ull pack2(float lo, float hi) {
    ull d; asm("mov.b64 %0,{%1,%2};" : "=l"(d) : "f"(lo), "f"(hi)); return d;
}
__device__ __forceinline__ float lo2(ull v) { return __uint_as_float((unsigned)v); }
__device__ __forceinline__ float hi2(ull v) { return __uint_as_float((unsigned)(v >> 32)); }

__device__ __align__(16) float g_E[128 * NOUT];
__device__ __align__(16) float g_CW[80 * NOUT];
__device__ __align__(16) float g_c[NOUT];

// ---------------- fast precompute (from v12, bench-verified) ----------------
__global__ void precompute_kernel(
    const float* __restrict__ embed,
    const float* __restrict__ w_state, const float* __restrict__ b_state,
    const float* __restrict__ w_top,   const float* __restrict__ b_top,
    const float* __restrict__ w_mem,   const float* __restrict__ b_mem,
    const float* __restrict__ w_buf,   const float* __restrict__ b_buf,
    const float* __restrict__ w_st,    const float* __restrict__ b_st)
{
    __shared__ __align__(16) float wcol[768];
    int n = blockIdx.x;
    const float* W; const float* bias; int N, col;
    if (n < 64)       { W = w_st;  bias = b_st;  N = 64;  col = n; }
    else if (n < 82)  { W = w_mem; bias = b_mem; N = 18;  col = n - 64; }
    else              { W = w_buf; bias = b_buf; N = 128; col = n - 82; }

    const int tid = threadIdx.x;
    for (int i = tid; i < 768; i += 448) wcol[i] = W[i * N + col];
    __syncthreads();

    float sp = 0.f;
    if (tid < 256) {
        int row = tid >> 1, half = tid & 1;
        const float4* er = (const float4*)(embed + row * 256 + half * 128);
        const float4* wc = (const float4*)(wcol + half * 128);
        float s0 = 0.f, s1 = 0.f, s2 = 0.f, s3 = 0.f;
#pragma unroll 8
        for (int h = 0; h < 32; h++) {
            float4 e = er[h], w4 = wc[h];
            s0 += e.x * w4.x; s1 += e.y * w4.y;
            s2 += e.z * w4.z; s3 += e.w * w4.w;
        }
        sp = (s0 + s1) + (s2 + s3);
    } else if (tid < 384) {
        int r = (tid - 256) >> 1, half = tid & 1;
        const float4* wr = (const float4*)(w_state + r * 256 + half * 128);
        const float4* wc = (const float4*)(wcol + 256 + half * 128);
        float s0 = 0.f, s1 = 0.f, s2 = 0.f, s3 = 0.f;
#pragma unroll 8
        for (int h = 0; h < 32; h++) {
            float4 e = wr[h], w4 = wc[h];
            s0 += e.x * w4.x; s1 += e.y * w4.y;
            s2 += e.z * w4.z; s3 += e.w * w4.w;
        }
        sp = (s0 + s1) + (s2 + s3);
    } else if (tid < 416) {
        int r = (tid - 384) >> 1, half = tid & 1;
        const float4* wr = (const float4*)(w_top + r * 256 + half * 128);
        const float4* wc = (const float4*)(wcol + 512 + half * 128);
        float s0 = 0.f, s1 = 0.f, s2 = 0.f, s3 = 0.f;
#pragma unroll 8
        for (int h = 0; h < 32; h++) {
            float4 e = wr[h], w4 = wc[h];
            s0 += e.x * w4.x; s1 += e.y * w4.y;
            s2 += e.z * w4.z; s3 += e.w * w4.w;
        }
        sp = (s0 + s1) + (s2 + s3);
    } else {
        int lane = tid - 416;
        const float4* bs = (const float4*)b_state;
        const float4* bt = (const float4*)b_top;
        const float4* wc = (const float4*)(wcol + 256);
#pragma unroll
        for (int j = 0; j < 4; j++) {
            int k = lane + j * 32;
            float4 b4 = (k < 64) ? bs[k] : bt[k - 64];
            float4 w4 = wc[k];
            sp += b4.x * w4.x + b4.y * w4.y + b4.z * w4.z + b4.w * w4.w;
        }
        float t = sp;
        for (int o = 16; o; o >>= 1) t += __shfl_xor_sync(0xffffffffu, t, o);
        if (lane == 0) g_c[n] = t + bias[col];
    }

    float pair = sp + __shfl_xor_sync(0xffffffffu, sp, 1);
    if ((tid & 1) == 0) {
        if (tid < 256)      g_E[(tid >> 1) * NOUT + n] = pair;
        else if (tid < 384) g_CW[((tid - 256) >> 1) * NOUT + n] = pair;
        else if (tid < 416) g_CW[(64 + ((tid - 384) >> 1)) * NOUT + n] = pair;
    }
}

// Shared floats:
//   sE    @ 0     : 26880          [tok][n]
//   sTok  @ 26880 : 2048 ints      [g][t]
//   sSt   @ 28928 : [slot][g][64] = 512    raw state exps (depth 4)
//   sTop  @ 29440 : [slot][g][16] = 128    raw top~ (depth 4)
//   sZmP  @ 29568 : [slot][g][8]  = 64     mem Z partials (depth 4)
//   sPr   @ 29632 : [ping][g][20] = 80     raw probs (depth 2, A-only)
//   sRows @ 29712 : [ping][g][3][16] = 192 stack rows 1-3 (A-only)
#define SMEM_FLOATS 29904

// register-resident soft-stack update (update warp). lane owns c=lane&3,
// depths d0..d0+7. 8 SHFLs exchange chunk boundaries. Publishes rows 1-3.
__device__ __forceinline__ void reg_stack_update(float4* r, const float* pr,
                                                 const float* zmp, int lane,
                                                 int c, int d0, float* rowsOut)
{
    float pe0 = pr[0], pe1 = pr[1];
    float4 za = *(const float4*)zmp;
    float4 zb = *(const float4*)(zmp + 4);
    float Zr = ((za.x + za.y) + (za.z + za.w)) + ((zb.x + zb.y) + (zb.z + zb.w));
    float iz = __fdividef(1.f, Zr);
    float ppop  = pe0 * iz;
    float pnoop = pe1 * iz;
    float ppush = (Zr - pe0 - pe1) * iz;
    float4 pv = ((const float4*)(pr + 4))[c];
    pv.x *= iz; pv.y *= iz; pv.z *= iz; pv.w *= iz;

    float4 oldR0 = r[0];
    float4 prev;
    prev.x = __shfl_up_sync(0xffffffffu, r[7].x, 4);
    prev.y = __shfl_up_sync(0xffffffffu, r[7].y, 4);
    prev.z = __shfl_up_sync(0xffffffffu, r[7].z, 4);
    prev.w = __shfl_up_sync(0xffffffffu, r[7].w, 4);
    if (d0 == 0) prev = make_float4(0.f, 0.f, 0.f, 0.f);
    float4 nxtLast;
    nxtLast.x = __shfl_down_sync(0xffffffffu, oldR0.x, 4);
    nxtLast.y = __shfl_down_sync(0xffffffffu, oldR0.y, 4);
    nxtLast.z = __shfl_down_sync(0xffffffffu, oldR0.z, 4);
    nxtLast.w = __shfl_down_sync(0xffffffffu, oldR0.w, 4);
    if (d0 == 56) nxtLast = make_float4((c == 0) ? 1.f : 0.f, 0.f, 0.f, 0.f);

#pragma unroll
    for (int i = 0; i < 8; i++) {
        float4 cur = r[i];
        float4 nxt = (i < 7) ? r[i + 1] : nxtLast;
        float4 o;
        o.x = ppush * prev.x + ppop * nxt.x + pnoop * cur.x;
        o.y = ppush * prev.y + ppop * nxt.y + pnoop * cur.y;
        o.z = ppush * prev.z + ppop * nxt.z + pnoop * cur.z;
        o.w = ppush * prev.w + ppop * nxt.w + pnoop * cur.w;
        if (d0 == 0 && i == 0) { o.x += pv.x; o.y += pv.y; o.z += pv.z; o.w += pv.w; }
        r[i] = o;
        prev = cur;
    }
    if (d0 == 0) {                 // lanes 0..3 hold depths 1..3 in r[1..3]
        ((float4*)rowsOut)[0 * 4 + c] = r[1];
        ((float4*)rowsOut)[1 * 4 + c] = r[2];
        ((float4*)rowsOut)[2 * 4 + c] = r[3];
    }
}

__global__ __launch_bounds__(NTHREADS, 1)
void stackrnn_kernel(const int* __restrict__ x, float* __restrict__ out)
{
    extern __shared__ float sm[];
    float* sE    = sm;
    int*   sTok  = (int*)(sm + 26880);
    float* sSt   = sm + 28928;
    float* sTop  = sm + 29440;
    float* sZmP  = sm + 29568;
    float* sPr   = sm + 29632;
    float* sRows = sm + 29712;

    const int tid  = threadIdx.x;
    const int wid  = tid >> 5;
    const int lane = tid & 31;
    const int b0   = blockIdx.x * 2;

    // ---- one-time setup ----
    {
        const float4* src = (const float4*)g_E;
        float4* dst = (float4*)sE;
        for (int i = tid; i < (128 * NOUT) / 4; i += NTHREADS) dst[i] = src[i];
    }
    for (int i = tid; i < 2 * SEQ; i += NTHREADS) {
        int g = i >> 10, r = i & 1023;
        sTok[i] = x[(size_t)(b0 + g) * SEQ + r];
    }
    if (tid < 128) sSt[tid] = 0.f;                            // slot 0
    if (tid < 32)  sTop[tid] = (tid == 0 || tid == 16) ? 1.f : 0.f;
    if (tid < 16)  sZmP[tid] = (tid == 0 || tid == 8) ? 1.f : 0.f;
    if (tid < 40)  sPr[tid]  = (tid == 1 || tid == 21) ? 1.f : 0.f;  // noop=1
    if (tid < 96)  sRows[tid] = ((tid & 15) == 0) ? 1.f : 0.f;       // ping0: null rows

    // ---- roles ----
    const bool isState  = (wid < 4);
    const bool isMem    = (wid == 4 || wid == 5);
    const bool isUpdate = (wid == 6 || wid == 7);
    const bool isBuf    = (wid >= 8);
    int g, mycol;
    if (isState)       { g = wid >> 1;  mycol = (wid & 1) * 32 + lane; }
    else if (isMem)    { g = wid - 4;   mycol = 64 + (lane < 18 ? lane : 0); }
    else if (isUpdate) { g = wid - 6;   mycol = 0; }
    else               { int idx = tid - 256; g = idx >> 7; mycol = 82 + (idx & 127); }

    ull W[40];
    float cn = 0.f;
    if (!isUpdate) {
        cn = g_c[mycol];
#pragma unroll
        for (int k = 0; k < 40; k++)
            W[k] = pack2(g_CW[(2 * k) * NOUT + mycol], g_CW[(2 * k + 1) * NOUT + mycol]);
    }
    __syncthreads();

    const size_t fsOff = (size_t)B_TOT * SEQ * 128;
    const size_t stOff = fsOff + (size_t)B_TOT * 64 * 16;

    if (isBuf) {
        // =================== GROUP B: buffer logits, lagged ===================
        const size_t outB = (size_t)(b0 + g) * (SEQ * 128);
        float baseNext = cn + sE[sTok[g * SEQ] * NOUT + mycol];
        for (int t = 0; t < SEQ; t++) {
            const int sCur = t & 3;
            BAR_SYNC(2 + sCur, 512);          // wait slot ready

            const ulonglong2* S = (const ulonglong2*)(sSt + sCur * 128 + g * 64);
            ull a0 = 0, a1 = 0, a2 = 0, a3 = 0;
            ull z0 = 0, z1 = 0, z2 = 0, z3 = 0;
#pragma unroll
            for (int i = 0; i < 8; i++) {
                ulonglong2 p = S[2 * i], q = S[2 * i + 1];
                a0 = ffma2(W[4 * i + 0], p.x, a0);  z0 = fadd2(z0, p.x);
                a1 = ffma2(W[4 * i + 1], p.y, a1);  z1 = fadd2(z1, p.y);
                a2 = ffma2(W[4 * i + 2], q.x, a2);  z2 = fadd2(z2, q.x);
                a3 = ffma2(W[4 * i + 3], q.y, a3);  z3 = fadd2(z3, q.y);
            }
            ull zz = fadd2(fadd2(z0, z1), fadd2(z2, z3));
            const float invZs = __fdividef(1.f, fmaxf(lo2(zz) + hi2(zz), 1e-30f));
            const ulonglong2* ZM = (const ulonglong2*)(sZmP + sCur * 16 + g * 8);
            ulonglong2 m0 = ZM[0], m1 = ZM[1];
            ull mm = fadd2(fadd2(m0.x, m0.y), fadd2(m1.x, m1.y));
            const float invZm = __fdividef(1.f, lo2(mm) + hi2(mm));

            const ulonglong2* T = (const ulonglong2*)(sTop + sCur * 32 + g * 16);
            ulonglong2 t0 = T[0], t1 = T[1], t2 = T[2], t3 = T[3];
            ull u0 = ffma2(W[32], t0.x, 0ULL), u1 = ffma2(W[33], t0.y, 0ULL);
            ull u2 = ffma2(W[34], t1.x, 0ULL), u3 = ffma2(W[35], t1.y, 0ULL);
            u0 = ffma2(W[36], t2.x, u0);  u1 = ffma2(W[37], t2.y, u1);
            u2 = ffma2(W[38], t3.x, u2);  u3 = ffma2(W[39], t3.y, u3);

            ull A = fadd2(fadd2(a0, a1), fadd2(a2, a3));
            ull U = fadd2(fadd2(u0, u1), fadd2(u2, u3));
            out[outB + (size_t)t * 128 + (mycol - 82)] =
                baseNext + invZs * (lo2(A) + hi2(A)) + invZm * (lo2(U) + hi2(U));

            if (t + 1 < SEQ)
                baseNext = cn + sE[sTok[g * SEQ + t + 1] * NOUT + mycol];
            BAR_ARRIVE(6 + sCur, 512);        // release slot
        }
    } else if (isUpdate) {
        // =================== UPDATE warps: register-resident stack =============
        const int c  = lane & 3;
        const int d0 = (lane >> 2) * 8;
        float4 r[8];
#pragma unroll
        for (int i = 0; i < 8; i++) r[i] = make_float4((c == 0) ? 1.f : 0.f, 0.f, 0.f, 0.f);

        BAR_ARRIVE(2 + 0, 512);
        for (int t = 0; t < SEQ; t++) {
            const int sCur  = t & 3;
            const int sNext = (t + 1) & 3;
            const int ping  = t & 1;
            if (t >= 3) BAR_SYNC(6 + sNext, 512);
            reg_stack_update(r, sPr + ping * 40 + g * 20, sZmP + sCur * 16 + g * 8,
                             lane, c, d0, sRows + (ping ^ 1) * 96 + g * 48);
            BAR_ARRIVE(2 + sNext, 512);
            BAR_SYNC(1, 256);
        }
        // epilogue: apply probs_{S-1} (sPr ping 0, sZmP slot 0), rows write unused
        reg_stack_update(r, sPr + 0 * 40 + g * 20, sZmP + 0 * 16 + g * 8,
                         lane, c, d0, sRows + 96 + g * 48);
        // final stack straight from registers
        const size_t base = fsOff + (size_t)(b0 + g) * 1024;
#pragma unroll
        for (int i = 0; i < 8; i++)
            *(float4*)(out + base + (d0 + i) * 16 + c * 4) = r[i];
    } else {
        // =================== STATE + MEM warps ===================
        float h0 = 0.f, h1 = 0.f, h2 = 0.f;       // normalized rows of stack_{t-1}
        float topc = 0.f;                          // raw row0 of next stack
        float cE0 = 0.f, cE1 = 1.f, cZp = 0.125f;  // probs_{-1}=noop; Z partial
        if (isMem && lane == 0) { h0 = h1 = h2 = 1.f; topc = 1.f; }

        float baseNext = cn + sE[sTok[g * SEQ] * NOUT + mycol];

        BAR_ARRIVE(2 + 0, 512);
        for (int t = 0; t < SEQ; t++) {
            const int sCur  = t & 3;
            const int sNext = (t + 1) & 3;
            const int ping  = t & 1;
            if (t >= 3) BAR_SYNC(6 + sNext, 512);

            // mem pre-dot: finish deferred Z + head rows (overlaps dot loads)
            if (isMem) {
                float Zp = cZp;
                Zp += __shfl_xor_sync(0xffffffffu, Zp, 4);
                Zp += __shfl_xor_sync(0xffffffffu, Zp, 8);
                Zp += __shfl_xor_sync(0xffffffffu, Zp, 16);
                float izp = __fdividef(1.f, Zp);
                float nh0 = topc * izp;
                float nh1 = ((Zp - cE0 - cE1) * h0 + cE0 * h2 + cE1 * h1) * izp;
                float s1 = 0.f, s2 = 0.f, s3 = 0.f;
                const float* RB = sRows + ping * 96 + g * 48;
                if (lane < 16) { s1 = RB[lane]; s2 = RB[16 + lane]; s3 = RB[32 + lane]; }
                float nh2 = ((Zp - cE0 - cE1) * s1 + cE0 * s3 + cE1 * s2) * izp;
                h0 = nh0; h1 = nh1; h2 = nh2;
            }

            // dot, state-Z folded into the same loads
            const ulonglong2* S = (const ulonglong2*)(sSt + sCur * 128 + g * 64);
            ull a0 = 0, a1 = 0, a2 = 0, a3 = 0;
            ull z0 = 0, z1 = 0, z2 = 0, z3 = 0;
#pragma unroll
            for (int i = 0; i < 8; i++) {
                ulonglong2 p = S[2 * i], q = S[2 * i + 1];
                a0 = ffma2(W[4 * i + 0], p.x, a0);  z0 = fadd2(z0, p.x);
                a1 = ffma2(W[4 * i + 1], p.y, a1);  z1 = fadd2(z1, p.y);
                a2 = ffma2(W[4 * i + 2], q.x, a2);  z2 = fadd2(z2, q.x);
                a3 = ffma2(W[4 * i + 3], q.y, a3);  z3 = fadd2(z3, q.y);
            }
            ull zz = fadd2(fadd2(z0, z1), fadd2(z2, z3));
            const float invZs = __fdividef(1.f, fmaxf(lo2(zz) + hi2(zz), 1e-30f));
            float invZm;
            if (isMem) {
                // Zm of probs_{t-1} == the Zp reduced above
                invZm = __fdividef(1.f, cZp + __shfl_xor_sync(0xffffffffu, cZp, 4)
                                        + __shfl_xor_sync(0xffffffffu, cZp, 8)
                                        + __shfl_xor_sync(0xffffffffu, cZp, 16));
            } else {
                const ulonglong2* ZM = (const ulonglong2*)(sZmP + sCur * 16 + g * 8);
                ulonglong2 m0 = ZM[0], m1 = ZM[1];
                ull mm = fadd2(fadd2(m0.x, m0.y), fadd2(m1.x, m1.y));
                invZm = __fdividef(1.f, lo2(mm) + hi2(mm));
            }
            const float base = baseNext;

            const ulonglong2* T = (const ulonglong2*)(sTop + sCur * 32 + g * 16);
            ulonglong2 t0 = T[0], t1 = T[1], t2 = T[2], t3 = T[3];
            ull u0 = ffma2(W[32], t0.x, 0ULL), u1 = ffma2(W[33], t0.y, 0ULL);
            ull u2 = ffma2(W[34], t1.x, 0ULL), u3 = ffma2(W[35], t1.y, 0ULL);
            u0 = ffma2(W[36], t2.x, u0);  u1 = ffma2(W[37], t2.y, u1);
            u2 = ffma2(W[38], t3.x, u2);  u3 = ffma2(W[39], t3.y, u3);

            ull A = fadd2(fadd2(a0, a1), fadd2(a2, a3));
            ull U = fadd2(fadd2(u0, u1), fadd2(u2, u3));
            const float r = base + invZs * (lo2(A) + hi2(A)) + invZm * (lo2(U) + hi2(U));

            if (t + 1 < SEQ)
                baseNext = cn + sE[sTok[g * SEQ + t + 1] * NOUT + mycol];

            if (isState) {
                sSt[sNext * 128 + g * 64 + mycol] = __expf(r);
            } else {  // mem
                float e = (lane < 18) ? __expf(r) : 0.f;
                float E0 = __shfl_sync(0xffffffffu, e, 0);
                float E1 = __shfl_sync(0xffffffffu, e, 1);
                float ep = __shfl_sync(0xffffffffu, e, 2 + (lane & 15));
                float topn = E1 * h0 + E0 * h1 + ep;          // raw, scale Zt
                if (lane < 16) sTop[sNext * 32 + g * 16 + lane] = topn;
                int pidx = (lane < 2) ? lane : lane + 2;
                if (lane < 18) sPr[(ping ^ 1) * 40 + g * 20 + pidx] = e;
                float pz = e;
                pz += __shfl_xor_sync(0xffffffffu, pz, 1);
                pz += __shfl_xor_sync(0xffffffffu, pz, 2);
                if ((lane & 3) == 0) sZmP[sNext * 16 + g * 8 + (lane >> 2)] = pz;
                topc = topn; cE0 = E0; cE1 = E1; cZp = pz;
            }
            BAR_ARRIVE(2 + sNext, 512);
            BAR_SYNC(1, 256);
        }

        // final state (slot 0 written at t=1023); bar.sync above made all
        // state-warp writes visible across the A group.
        if (tid < 128) {
            int gg = tid >> 6;
            float zs = 0.f;
            for (int j = 0; j < 64; j++) zs += sSt[gg * 64 + j];
            out[stOff + (size_t)(b0 + gg) * 64 + (tid & 63)] =
                sSt[tid] * __fdividef(1.f, fmaxf(zs, 1e-30f));
        }
    }
}

extern "C" void kernel_launch(void* const* d_in, const int* in_sizes, int n_in,
                              void* d_out, int out_size)
{
    const int*   x       = (const int*)  d_in[0];
    const float* embed   = (const float*)d_in[1];
    const float* w_state = (const float*)d_in[2];
    const float* b_state = (const float*)d_in[3];
    const float* w_top   = (const float*)d_in[4];
    const float* b_top   = (const float*)d_in[5];
    const float* w_mem   = (const float*)d_in[6];
    const float* b_mem   = (const float*)d_in[7];
    const float* w_buf   = (const float*)d_in[8];
    const float* b_buf   = (const float*)d_in[9];
    const float* w_st    = (const float*)d_in[10];
    const float* b_st    = (const float*)d_in[11];
    float* out = (float*)d_out;

    precompute_kernel<<<NOUT, 448>>>(embed, w_state, b_state, w_top, b_top,
                                     w_mem, b_mem, w_buf, b_buf, w_st, b_st);

    cudaFuncSetAttribute(stackrnn_kernel,
                         cudaFuncAttributeMaxDynamicSharedMemorySize,
                         SMEM_FLOATS * sizeof(float));
    stackrnn_kernel<<<B_TOT / 2, NTHREADS, SMEM_FLOATS * sizeof(float)>>>(x, out);
}